// round 7
// baseline (speedup 1.0000x reference)
#include <cuda_runtime.h>

// Problem constants (fixed by the dataset)
#define T_LEN 4096
#define B_SZ  32
#define C_SZ  300
#define W_SZ  128
#define C4    (C_SZ / 4)     // 75 float4 per (t,b) row
#define ROW4  (B_SZ * C4)    // 2400 float4 per t-slice
#define NTHR  480            // 2400 = 480 * 5 exactly
#define UNROLL 5

// Fused kernel: one block per t (R3 structure — proven best shape).
// pe gather is branchless: clamped index + FMA weight, so each iteration's
// x-load (DRAM) and pe-load (L2 hit) issue back-to-back with no divergence.
// __launch_bounds__(480, 4) pins regs at 32 to protect 4-blocks/SM occupancy.
__global__ void __launch_bounds__(NTHR, 4) k_fused(const float4* __restrict__ x,
                                                   const float4* __restrict__ pe,
                                                   const int*    __restrict__ dur,
                                                   float4*       __restrict__ out) {
    __shared__ int s_pos[B_SZ];
    const int t    = blockIdx.x;
    const int warp = threadIdx.x >> 5;
    const int lane = threadIdx.x & 31;
    const int tid  = threadIdx.x;

    // ---- prologue: segment position for 4 samples per warp (warps 0-7) ----
    if (warp < 8) {
#pragma unroll
        for (int k = 0; k < 4; k++) {
            const int b = warp * 4 + k;
            int4 d4 = *(const int4*)(dur + b * W_SZ + lane * 4);
            int s = d4.x + d4.y + d4.z + d4.w;
            int incl = s;
#pragma unroll
            for (int o = 1; o < 32; o <<= 1) {
                int vv = __shfl_up_sync(0xffffffffu, incl, o);
                if (lane >= o) incl += vv;
            }
            int base = incl - s;                   // exclusive prefix across lanes
            int st0 = base;
            int st1 = base + d4.x;
            int st2 = st1 + d4.y;
            int st3 = st2 + d4.z;
            int tot = __shfl_sync(0xffffffffu, incl, 31);

            // Largest start <= t: starts nondecreasing across lanes.
            unsigned m = __ballot_sync(0xffffffffu, st0 <= t);
            int L = 31 - __clz(m);
            int loc = st0;
            if (st1 <= t) loc = st1;
            if (st2 <= t) loc = st2;
            if (st3 <= t) loc = st3;
            int seg = __shfl_sync(0xffffffffu, loc, L);

            if (lane == 0) s_pos[b] = (t < tot) ? (t - seg) : -1;
        }
    }
    __syncthreads();

    // ---- streaming add: branchless pe gather, paired x/pe loads ----
    const float4* xrow = x + (size_t)t * ROW4;
    float4*       orow = out + (size_t)t * ROW4;

#pragma unroll
    for (int i = 0; i < UNROLL; i++) {
        int j  = tid + i * NTHR;
        int b  = j / C4;                          // constant divide -> mul/shift
        int c4 = j - b * C4;
        int p  = s_pos[b];
        float w  = (p >= 0) ? 1.0f : 0.0f;        // mask as FMA weight
        int   pc = (p >= 0) ? p : 0;              // clamped row (always valid)

        float4 v  = __ldcs(xrow + j);             // streaming read (DRAM)
        float4 pv = __ldg(pe + pc * C4 + c4);     // L2-resident table
        v.x = fmaf(pv.x, w, v.x);
        v.y = fmaf(pv.y, w, v.y);
        v.z = fmaf(pv.z, w, v.z);
        v.w = fmaf(pv.w, w, v.w);
        __stcs(orow + j, v);                      // streaming write
    }
}

extern "C" void kernel_launch(void* const* d_in, const int* in_sizes, int n_in,
                              void* d_out, int out_size) {
    const float* x  = (const float*)d_in[0];
    const float* pe = (const float*)d_in[1];
    const int*   du = (const int*)d_in[2];
    // d_in[3] = train flag, unused by the reference math.
    k_fused<<<T_LEN, NTHR>>>((const float4*)x, (const float4*)pe, du, (float4*)d_out);
}

// round 8
// speedup vs baseline: 1.0705x; 1.0705x over previous
#include <cuda_runtime.h>

// Problem constants (fixed by the dataset)
#define T_LEN 4096
#define B_SZ  32
#define C_SZ  300
#define W_SZ  128
#define C4    (C_SZ / 4)     // 75 float4 per (t,b) row
#define ROW4  (B_SZ * C4)    // 2400 float4 per t-slice
#define NTHR  480            // 2400 = 480 * 5 exactly
#define UNROLL 5

// Fused kernel: one block per t (R3 frontier shape: regs 32, occ ~78%).
// Delta vs R3: pe gather bypasses L1 (__ldcg) — zero intra-block reuse, so
// L1 caching it only pollutes the L1tex wavefront queue shared with the
// x-stream and stores.
__global__ void __launch_bounds__(NTHR) k_fused(const float4* __restrict__ x,
                                                const float4* __restrict__ pe,
                                                const int*    __restrict__ dur,
                                                float4*       __restrict__ out) {
    __shared__ int s_pos[B_SZ];
    const int t    = blockIdx.x;
    const int warp = threadIdx.x >> 5;
    const int lane = threadIdx.x & 31;
    const int tid  = threadIdx.x;

    // ---- prologue: segment position for 4 samples per warp (warps 0-7) ----
    if (warp < 8) {
#pragma unroll
        for (int k = 0; k < 4; k++) {
            const int b = warp * 4 + k;
            int4 d4 = __ldg((const int4*)(dur + b * W_SZ + lane * 4));
            int s = d4.x + d4.y + d4.z + d4.w;
            int incl = s;
#pragma unroll
            for (int o = 1; o < 32; o <<= 1) {
                int vv = __shfl_up_sync(0xffffffffu, incl, o);
                if (lane >= o) incl += vv;
            }
            int base = incl - s;                   // exclusive prefix across lanes
            int st0 = base;
            int st1 = base + d4.x;
            int st2 = st1 + d4.y;
            int st3 = st2 + d4.z;
            int tot = __shfl_sync(0xffffffffu, incl, 31);

            // Largest start <= t: starts nondecreasing across lanes.
            unsigned m = __ballot_sync(0xffffffffu, st0 <= t);
            int L = 31 - __clz(m);
            int loc = st0;
            if (st1 <= t) loc = st1;
            if (st2 <= t) loc = st2;
            if (st3 <= t) loc = st3;
            int seg = __shfl_sync(0xffffffffu, loc, L);

            if (lane == 0) s_pos[b] = (t < tot) ? (t - seg) : -1;
        }
    }
    __syncthreads();

    // ---- streaming add: exact unroll, batched x loads for MLP ----
    const float4* xrow = x + (size_t)t * ROW4;
    float4*       orow = out + (size_t)t * ROW4;

    float4 v[UNROLL];
    int    bb[UNROLL], cc[UNROLL];
#pragma unroll
    for (int i = 0; i < UNROLL; i++) {
        int j = tid + i * NTHR;
        bb[i] = j / C4;                    // constant divide -> mul/shift
        cc[i] = j - bb[i] * C4;
        v[i]  = __ldcs(xrow + j);          // streaming read (evict-first)
    }
#pragma unroll
    for (int i = 0; i < UNROLL; i++) {
        int p = s_pos[bb[i]];
        if (p >= 0) {
            float4 pv = __ldcg(pe + p * C4 + cc[i]);  // L2-only: no L1 pollution
            v[i].x += pv.x; v[i].y += pv.y; v[i].z += pv.z; v[i].w += pv.w;
        }
    }
#pragma unroll
    for (int i = 0; i < UNROLL; i++) {
        __stcs(orow + tid + i * NTHR, v[i]);          // streaming write
    }
}

extern "C" void kernel_launch(void* const* d_in, const int* in_sizes, int n_in,
                              void* d_out, int out_size) {
    const float* x  = (const float*)d_in[0];
    const float* pe = (const float*)d_in[1];
    const int*   du = (const int*)d_in[2];
    // d_in[3] = train flag, unused by the reference math.
    k_fused<<<T_LEN, NTHR>>>((const float4*)x, (const float4*)pe, du, (float4*)d_out);
}